// round 11
// baseline (speedup 1.0000x reference)
#include <cuda_runtime.h>
#include <cuda_bf16.h>

#define B_      8
#define NVAL    1024
#define MVAL    1024
#define CIN     8
#define CREP    9
#define COUT    16

#define NBINS   128
#define BINLO   (-5.0f)
#define BINW    (NBINS / 10.0f)      // 12.8 bins per unit over [-5, 5]
#define XPAD    (NVAL + 2)           // +2 sentinel slots for paired loads
#define WARPS   8
#define NTHREADS 256
#define TGRP    32                   // sorted-t per block
#define NGRP    (MVAL / TGRP)        // 32 t-groups per batch

typedef unsigned long long u64;

__device__ __align__(16) float g_xs  [B_ * XPAD];
__device__ __align__(16) float g_ysA [B_ * XPAD * 4];
__device__ __align__(16) float g_ysB [B_ * XPAD * 4];
__device__ float g_ts  [B_ * NVAL];
__device__ int   g_tidx[B_ * NVAL];
__device__ int   g_bstart[B_ * (NBINS + 1)];

__device__ __forceinline__ u64 pack2(float lo, float hi) {
    u64 r; asm("mov.b64 %0, {%1, %2};" : "=l"(r) : "f"(lo), "f"(hi)); return r;
}
__device__ __forceinline__ void unpack2(u64 v, float& lo, float& hi) {
    asm("mov.b64 {%0, %1}, %2;" : "=f"(lo), "=f"(hi) : "l"(v));
}
__device__ __forceinline__ u64 add2(u64 a, u64 b) {
    u64 r; asm("add.rn.f32x2 %0, %1, %2;" : "=l"(r) : "l"(a), "l"(b)); return r;
}
__device__ __forceinline__ u64 mul2(u64 a, u64 b) {
    u64 r; asm("mul.rn.f32x2 %0, %1, %2;" : "=l"(r) : "l"(a), "l"(b)); return r;
}
__device__ __forceinline__ u64 fma2(u64 a, u64 b, u64 c) {
    u64 r; asm("fma.rn.f32x2 %0, %1, %2, %3;" : "=l"(r) : "l"(a), "l"(b), "l"(c)); return r;
}
__device__ __forceinline__ float ex2(float x) {
    float r; asm("ex2.approx.f32 %0, %1;" : "=f"(r) : "f"(x)); return r;
}

// ---------------- Prelude: deterministic bucket sort of x (+y payload) and t ----
// grid = 16: blockIdx = b*2 + phase. 1024 threads, one element each.
__global__ __launch_bounds__(1024)
void convcnp_sort(const float* __restrict__ gx,
                  const float* __restrict__ gy,
                  const float* __restrict__ gt)
{
    __shared__ int whist[32 * NBINS];   // per-warp per-bin (count -> warp-prefix)
    __shared__ int prefix[NBINS + 1];

    const int b     = blockIdx.x >> 1;
    const int phase = blockIdx.x & 1;
    const int tid   = threadIdx.x;
    const int lane  = tid & 31;
    const int w     = tid >> 5;

    const float v = phase == 0 ? gx[b * NVAL + tid] : gt[b * NVAL + tid];
    int bin = (int)((v - BINLO) * BINW);
    bin = bin < 0 ? 0 : (bin > NBINS - 1 ? NBINS - 1 : bin);

    for (int j = tid; j < 32 * NBINS; j += 1024) whist[j] = 0;
    __syncthreads();

    const unsigned mask   = __match_any_sync(0xffffffffu, bin);
    const int      before = __popc(mask & ((1u << lane) - 1u));
    if ((int)(__ffs(mask) - 1) == lane)
        whist[w * NBINS + bin] = __popc(mask);
    __syncthreads();

    if (tid < NBINS) {                 // column prefix over warps + totals
        int run = 0;
        #pragma unroll
        for (int ww = 0; ww < 32; ww++) {
            int t = whist[ww * NBINS + tid];
            whist[ww * NBINS + tid] = run;
            run += t;
        }
        prefix[tid] = run;             // temp: totals
    }
    __syncthreads();

    if (tid < 32) {                    // exclusive scan of 128 totals (warp 0)
        int h0 = prefix[4 * tid], h1 = prefix[4 * tid + 1];
        int h2 = prefix[4 * tid + 2], h3 = prefix[4 * tid + 3];
        int s = h0 + h1 + h2 + h3, sc = s;
        #pragma unroll
        for (int off = 1; off < 32; off <<= 1) {
            int t = __shfl_up_sync(0xffffffffu, sc, off);
            if (lane >= off) sc += t;
        }
        int base = sc - s;
        __syncwarp();                  // all reads of prefix[] done before writes
        prefix[4 * tid]     = base;
        prefix[4 * tid + 1] = base + h0;
        prefix[4 * tid + 2] = base + h0 + h1;
        prefix[4 * tid + 3] = base + h0 + h1 + h2;
        if (tid == 31) prefix[NBINS] = sc;  // = 1024
    }
    __syncthreads();

    const int rank = prefix[bin] + whist[w * NBINS + bin] + before;

    if (phase == 0) {
        g_xs[b * XPAD + rank] = v;
        const float4* y4 = (const float4*)(gy + (size_t)(b * NVAL + tid) * CIN);
        ((float4*)g_ysA)[b * XPAD + rank] = y4[0];
        ((float4*)g_ysB)[b * XPAD + rank] = y4[1];
        if (tid <= NBINS) g_bstart[b * (NBINS + 1) + tid] = prefix[tid];
        if (tid < 2) {                 // sentinels: huge x -> exp underflows to 0
            g_xs[b * XPAD + NVAL + tid] = 1.0e9f;
            ((float4*)g_ysA)[b * XPAD + NVAL + tid] = make_float4(0, 0, 0, 0);
            ((float4*)g_ysB)[b * XPAD + NVAL + tid] = make_float4(0, 0, 0, 0);
        }
    } else {
        g_ts  [b * NVAL + rank] = v;
        g_tidx[b * NVAL + rank] = tid;
    }
}

// ---------------- Main: windowed accumulation over sorted x ---------------------
__global__ __launch_bounds__(NTHREADS)
void convcnp_main(const float* __restrict__ gsigma,
                  const float* __restrict__ gW,
                  const float* __restrict__ gbias,
                  float* __restrict__ gout)
{
    __shared__ float s_red [WARPS * TGRP * CREP];   // 9216B
    __shared__ float s_tot [TGRP * CREP];           // 288
    __shared__ int   s_midx[TGRP];

    const int b    = blockIdx.x >> 5;       // NGRP = 32
    const int g    = blockIdx.x & (NGRP - 1);
    const int tid  = threadIdx.x;
    const int lane = tid & 31;
    const int w    = tid >> 5;

    float kk[CREP];
    float smax = 0.0f;
    bool same = true;
    #pragma unroll
    for (int c = 0; c < CREP; c++) {
        float s = __expf(gsigma[c]);
        smax = fmaxf(smax, s);
        kk[c] = -0.5f * 1.4426950408889634f / (s * s);
        if (c > 0 && kk[c] != kk[0]) same = false;
    }
    const float R = 8.5f * smax;            // dropped weight < e^-36 << 1e-8 floor

    const float tmv = g_ts[b * NVAL + g * TGRP + lane];
    if (w == 0) s_midx[lane] = g_tidx[b * NVAL + g * TGRP + lane];

    // Block-uniform window over sorted x (t sorted -> lanes 0/31 are extremes)
    const float tlo = __shfl_sync(0xffffffffu, tmv, 0)  - R;
    const float thi = __shfl_sync(0xffffffffu, tmv, 31) + R;
    int blo = (int)((tlo - BINLO) * BINW);
    int bhi = (int)((thi - BINLO) * BINW);
    blo = blo < 0 ? 0 : (blo > NBINS - 1 ? NBINS - 1 : blo);
    bhi = bhi < 0 ? 0 : (bhi > NBINS - 1 ? NBINS - 1 : bhi);
    const int n_lo = g_bstart[b * (NBINS + 1) + blo] & ~1;     // even align (extra
    const int n_hi = g_bstart[b * (NBINS + 1) + bhi + 1];      //  pt: weight ~0)
    const int cnt  = n_hi - n_lo;
    // R10 BUG WAS HERE: divisor must be WARPS (8 slices), not 2*WARPS.
    const int slice = ((cnt + WARPS - 1) / WARPS + 1) & ~1;    // even, 8*slice>=cnt
    const int s0 = n_lo + w * slice;
    const int e0 = min(s0 + slice, n_hi);   // pair at odd e0 may overrun 1 pt:
                                            // sentinel or weight < e^-36, harmless
    const float* xs  = g_xs  + b * XPAD;
    const float* ysA = g_ysA + (size_t)b * XPAD * 4;
    const float* ysB = g_ysB + (size_t)b * XPAD * 4;

    float sum[CREP];

    if (same) {
        const u64 ntm2 = pack2(-tmv, -tmv);
        const u64 kk2  = pack2(kk[0], kk[0]);
        u64 dd0 = 0, A12 = 0, A34 = 0, A56 = 0, A78 = 0;

        #pragma unroll 2
        for (int n = s0; n < e0; n += 2) {
            u64 x2 = *(const u64*)&xs[n];                 // broadcast LDG (L1)
            ulonglong2 yA = *(const ulonglong2*)&ysA[n * 4];
            ulonglong2 yB = *(const ulonglong2*)&ysB[n * 4];
            ulonglong2 zA = *(const ulonglong2*)&ysA[(n + 1) * 4];
            ulonglong2 zB = *(const ulonglong2*)&ysB[(n + 1) * 4];

            u64 a   = add2(x2, ntm2);                     // x - t
            u64 arg = mul2(mul2(a, a), kk2);              // kk0*(x-t)^2 (<=0)
            float f0, f1; unpack2(arg, f0, f1);
            float e0v = ex2(f0), e1v = ex2(f1);
            dd0 = add2(dd0, pack2(e0v, e1v));
            u64 e00 = pack2(e0v, e0v), e11 = pack2(e1v, e1v);
            A12 = fma2(e00, yA.x, A12);  A34 = fma2(e00, yA.y, A34);
            A56 = fma2(e00, yB.x, A56);  A78 = fma2(e00, yB.y, A78);
            A12 = fma2(e11, zA.x, A12);  A34 = fma2(e11, zA.y, A34);
            A56 = fma2(e11, zB.x, A56);  A78 = fma2(e11, zB.y, A78);
        }
        float lo, hi;
        unpack2(dd0, lo, hi);  sum[0] = lo + hi;
        unpack2(A12, sum[1], sum[2]); unpack2(A34, sum[3], sum[4]);
        unpack2(A56, sum[5], sum[6]); unpack2(A78, sum[7], sum[8]);
    } else {
        #pragma unroll
        for (int c = 0; c < CREP; c++) sum[c] = 0.0f;
        for (int n = s0; n < e0; n++) {
            float a = xs[n] - tmv, d = a * a;
            const float4 ya = *(const float4*)&ysA[n * 4];
            const float4 yb = *(const float4*)&ysB[n * 4];
            sum[0] += ex2(d * kk[0]);
            sum[1] = fmaf(ex2(d * kk[1]), ya.x, sum[1]);
            sum[2] = fmaf(ex2(d * kk[2]), ya.y, sum[2]);
            sum[3] = fmaf(ex2(d * kk[3]), ya.z, sum[3]);
            sum[4] = fmaf(ex2(d * kk[4]), ya.w, sum[4]);
            sum[5] = fmaf(ex2(d * kk[5]), yb.x, sum[5]);
            sum[6] = fmaf(ex2(d * kk[6]), yb.y, sum[6]);
            sum[7] = fmaf(ex2(d * kk[7]), yb.z, sum[7]);
            sum[8] = fmaf(ex2(d * kk[8]), yb.w, sum[8]);
        }
    }

    #pragma unroll
    for (int c = 0; c < CREP; c++)
        s_red[(w * TGRP + lane) * CREP + c] = sum[c];
    __syncthreads();

    for (int i = tid; i < TGRP * CREP; i += NTHREADS) {
        float s = 0.0f;
        #pragma unroll
        for (int ww = 0; ww < WARPS; ww++)
            s += s_red[ww * (TGRP * CREP) + i];
        s_tot[i] = s;
    }
    __syncthreads();

    // GEMV: 32 m x 16 o = 512 outputs, 2 per thread; scatter by original index.
    #pragma unroll
    for (int k = 0; k < 2; k++) {
        const int idx = tid + k * NTHREADS;
        const int mm  = idx >> 4;
        const int o   = idx & (COUT - 1);
        const float density = s_tot[mm * CREP];
        const float inv = 1.0f / (density + 1e-8f);
        float r = __ldg(&gbias[o]) + __ldg(&gW[o * CREP]) * density;
        #pragma unroll
        for (int c = 1; c < CREP; c++)
            r = fmaf(__ldg(&gW[o * CREP + c]), s_tot[mm * CREP + c] * inv, r);
        gout[((size_t)b * MVAL + s_midx[mm]) * COUT + o] = r;
    }
}

extern "C" void kernel_launch(void* const* d_in, const int* in_sizes, int n_in,
                              void* d_out, int out_size) {
    const float* x     = (const float*)d_in[0];
    const float* y     = (const float*)d_in[1];
    const float* t     = (const float*)d_in[2];
    const float* sigma = (const float*)d_in[3];
    const float* W     = (const float*)d_in[4];
    const float* bias  = (const float*)d_in[5];
    float* out = (float*)d_out;

    convcnp_sort<<<B_ * 2, 1024>>>(x, y, t);                    // 16 blocks
    convcnp_main<<<B_ * NGRP, NTHREADS>>>(sigma, W, bias, out); // 256 blocks
}

// round 13
// speedup vs baseline: 1.2388x; 1.2388x over previous
#include <cuda_runtime.h>
#include <cuda_bf16.h>

#define B_      8
#define NVAL    1024
#define MVAL    1024
#define CIN     8
#define CREP    9
#define COUT    16

#define NBINS   128
#define BINLO   (-5.0f)
#define BINW    (NBINS / 10.0f)      // 12.8 bins per unit over [-5, 5]
#define XPAD    (NVAL + 2)           // +2 sentinel slots for paired loads
#define WARPS   8
#define NTHREADS 256
#define TGRP    32                   // sorted-t per block (lane = t)
#define NGRP    (MVAL / TGRP)        // 32 t-groups per batch
#define CHUNK   512                  // window points staged per smem pass

typedef unsigned long long u64;

__device__ __align__(16) float g_xs  [B_ * XPAD];
__device__ __align__(16) float g_ysA [B_ * XPAD * 4];
__device__ __align__(16) float g_ysB [B_ * XPAD * 4];
__device__ float g_ts  [B_ * NVAL];
__device__ int   g_tidx[B_ * NVAL];
__device__ int   g_bstart[B_ * (NBINS + 1)];

__device__ __forceinline__ u64 pack2(float lo, float hi) {
    u64 r; asm("mov.b64 %0, {%1, %2};" : "=l"(r) : "f"(lo), "f"(hi)); return r;
}
__device__ __forceinline__ void unpack2(u64 v, float& lo, float& hi) {
    asm("mov.b64 {%0, %1}, %2;" : "=f"(lo), "=f"(hi) : "l"(v));
}
__device__ __forceinline__ u64 add2(u64 a, u64 b) {
    u64 r; asm("add.rn.f32x2 %0, %1, %2;" : "=l"(r) : "l"(a), "l"(b)); return r;
}
__device__ __forceinline__ u64 mul2(u64 a, u64 b) {
    u64 r; asm("mul.rn.f32x2 %0, %1, %2;" : "=l"(r) : "l"(a), "l"(b)); return r;
}
__device__ __forceinline__ u64 fma2(u64 a, u64 b, u64 c) {
    u64 r; asm("fma.rn.f32x2 %0, %1, %2, %3;" : "=l"(r) : "l"(a), "l"(b), "l"(c)); return r;
}
__device__ __forceinline__ float ex2(float x) {
    float r; asm("ex2.approx.f32 %0, %1;" : "=f"(r) : "f"(x)); return r;
}

// ---------------- Prelude: deterministic bucket sort of x (+y payload) and t ----
__global__ __launch_bounds__(1024)
void convcnp_sort(const float* __restrict__ gx,
                  const float* __restrict__ gy,
                  const float* __restrict__ gt)
{
    __shared__ int whist[32 * NBINS];
    __shared__ int prefix[NBINS + 1];

    const int b     = blockIdx.x >> 1;
    const int phase = blockIdx.x & 1;
    const int tid   = threadIdx.x;
    const int lane  = tid & 31;
    const int w     = tid >> 5;

    const float v = phase == 0 ? gx[b * NVAL + tid] : gt[b * NVAL + tid];
    int bin = (int)((v - BINLO) * BINW);
    bin = bin < 0 ? 0 : (bin > NBINS - 1 ? NBINS - 1 : bin);

    for (int j = tid; j < 32 * NBINS; j += 1024) whist[j] = 0;
    __syncthreads();

    const unsigned mask   = __match_any_sync(0xffffffffu, bin);
    const int      before = __popc(mask & ((1u << lane) - 1u));
    if ((int)(__ffs(mask) - 1) == lane)
        whist[w * NBINS + bin] = __popc(mask);
    __syncthreads();

    if (tid < NBINS) {
        int run = 0;
        #pragma unroll
        for (int ww = 0; ww < 32; ww++) {
            int t = whist[ww * NBINS + tid];
            whist[ww * NBINS + tid] = run;
            run += t;
        }
        prefix[tid] = run;
    }
    __syncthreads();

    if (tid < 32) {
        int h0 = prefix[4 * tid], h1 = prefix[4 * tid + 1];
        int h2 = prefix[4 * tid + 2], h3 = prefix[4 * tid + 3];
        int s = h0 + h1 + h2 + h3, sc = s;
        #pragma unroll
        for (int off = 1; off < 32; off <<= 1) {
            int t = __shfl_up_sync(0xffffffffu, sc, off);
            if (lane >= off) sc += t;
        }
        int base = sc - s;
        __syncwarp();
        prefix[4 * tid]     = base;
        prefix[4 * tid + 1] = base + h0;
        prefix[4 * tid + 2] = base + h0 + h1;
        prefix[4 * tid + 3] = base + h0 + h1 + h2;
        if (tid == 31) prefix[NBINS] = sc;
    }
    __syncthreads();

    const int rank = prefix[bin] + whist[w * NBINS + bin] + before;

    if (phase == 0) {
        g_xs[b * XPAD + rank] = v;
        const float4* y4 = (const float4*)(gy + (size_t)(b * NVAL + tid) * CIN);
        ((float4*)g_ysA)[b * XPAD + rank] = y4[0];
        ((float4*)g_ysB)[b * XPAD + rank] = y4[1];
        if (tid <= NBINS) g_bstart[b * (NBINS + 1) + tid] = prefix[tid];
        if (tid < 2) {
            g_xs[b * XPAD + NVAL + tid] = 1.0e9f;
            ((float4*)g_ysA)[b * XPAD + NVAL + tid] = make_float4(0, 0, 0, 0);
            ((float4*)g_ysB)[b * XPAD + NVAL + tid] = make_float4(0, 0, 0, 0);
        }
    } else {
        g_ts  [b * NVAL + rank] = v;
        g_tidx[b * NVAL + rank] = tid;
    }
}

// ---------------- Main: windowed accumulation, smem-chunked ---------------------
__global__ __launch_bounds__(NTHREADS)
void convcnp_main(const float* __restrict__ gsigma,
                  const float* __restrict__ gW,
                  const float* __restrict__ gbias,
                  float* __restrict__ gout)
{
    // R12 BUG: these were unaligned (s_x = 2056B pushed s_yA to a mod-16=8
    // offset -> LDS.128 misaligned-address trap). All wide-accessed shared
    // arrays must be 16B-aligned.
    __shared__ __align__(16) float s_x [CHUNK + 4];
    __shared__ __align__(16) float s_yA[(CHUNK + 2) * 4];
    __shared__ __align__(16) float s_yB[(CHUNK + 2) * 4];
    __shared__ __align__(16) float s_red [WARPS * TGRP * CREP];
    __shared__ __align__(16) float s_tot [TGRP * CREP];
    __shared__ int   s_midx[TGRP];

    const int g    = blockIdx.x & (NGRP - 1);   // vary g fastest: mixes window
    const int b    = blockIdx.x >> 5;           //  sizes across adjacent SMs
    const int tid  = threadIdx.x;
    const int lane = tid & 31;
    const int w    = tid >> 5;

    float kk[CREP];
    float smax = 0.0f;
    bool same = true;
    #pragma unroll
    for (int c = 0; c < CREP; c++) {
        float s = __expf(gsigma[c]);
        smax = fmaxf(smax, s);
        kk[c] = -0.5f * 1.4426950408889634f / (s * s);
        if (c > 0 && kk[c] != kk[0]) same = false;
    }
    const float R = 8.5f * smax;                // dropped weight < e^-36

    const float tmv = g_ts[b * NVAL + g * TGRP + lane];
    if (w == 0) s_midx[lane] = g_tidx[b * NVAL + g * TGRP + lane];

    const float tlo = __shfl_sync(0xffffffffu, tmv, 0)  - R;
    const float thi = __shfl_sync(0xffffffffu, tmv, 31) + R;
    int blo = (int)((tlo - BINLO) * BINW);
    int bhi = (int)((thi - BINLO) * BINW);
    blo = blo < 0 ? 0 : (blo > NBINS - 1 ? NBINS - 1 : blo);
    bhi = bhi < 0 ? 0 : (bhi > NBINS - 1 ? NBINS - 1 : bhi);
    const int n_lo = g_bstart[b * (NBINS + 1) + blo] & ~1;
    const int n_hi = g_bstart[b * (NBINS + 1) + bhi + 1];

    const float*  xs  = g_xs + b * XPAD;
    const float4* gA4 = (const float4*)g_ysA + (size_t)b * XPAD;
    const float4* gB4 = (const float4*)g_ysB + (size_t)b * XPAD;

    float sum[CREP];
    const u64 ntm2 = pack2(-tmv, -tmv);
    const u64 kk2  = pack2(kk[0], kk[0]);
    u64 dd0 = 0, A12 = 0, A34 = 0, A56 = 0, A78 = 0;
    #pragma unroll
    for (int c = 0; c < CREP; c++) sum[c] = 0.0f;

    for (int c0 = n_lo; c0 < n_hi; c0 += CHUNK) {
        const int cnt_c = min(CHUNK, n_hi - c0);

        // Stage chunk (coalesced) + per-chunk sentinels.
        for (int i = tid; i < cnt_c; i += NTHREADS) {
            s_x[i] = xs[c0 + i];
            ((float4*)s_yA)[i] = gA4[c0 + i];
            ((float4*)s_yB)[i] = gB4[c0 + i];
        }
        if (tid < 2) {
            s_x[cnt_c + tid] = 1.0e9f;
            ((float4*)s_yA)[cnt_c + tid] = make_float4(0, 0, 0, 0);
            ((float4*)s_yB)[cnt_c + tid] = make_float4(0, 0, 0, 0);
        }
        __syncthreads();

        const int slice = (((cnt_c + WARPS - 1) / WARPS) + 1) & ~1;  // even
        const int s0 = w * slice;
        const int e0 = min(s0 + slice, cnt_c);

        if (same) {
            #pragma unroll 2
            for (int n = s0; n < e0; n += 2) {
                u64 x2 = *(const u64*)&s_x[n];
                ulonglong2 yA = *(const ulonglong2*)&s_yA[n * 4];
                ulonglong2 yB = *(const ulonglong2*)&s_yB[n * 4];
                ulonglong2 zA = *(const ulonglong2*)&s_yA[(n + 1) * 4];
                ulonglong2 zB = *(const ulonglong2*)&s_yB[(n + 1) * 4];

                u64 a   = add2(x2, ntm2);                 // x - t
                u64 arg = mul2(mul2(a, a), kk2);          // kk0*(x-t)^2 (<=0)
                float f0, f1; unpack2(arg, f0, f1);
                float e0v = ex2(f0), e1v = ex2(f1);
                dd0 = add2(dd0, pack2(e0v, e1v));
                u64 e00 = pack2(e0v, e0v), e11 = pack2(e1v, e1v);
                A12 = fma2(e00, yA.x, A12);  A34 = fma2(e00, yA.y, A34);
                A56 = fma2(e00, yB.x, A56);  A78 = fma2(e00, yB.y, A78);
                A12 = fma2(e11, zA.x, A12);  A34 = fma2(e11, zA.y, A34);
                A56 = fma2(e11, zB.x, A56);  A78 = fma2(e11, zB.y, A78);
            }
        } else {
            for (int n = s0; n < e0; n++) {
                float a = s_x[n] - tmv, d = a * a;
                const float4 ya = *(const float4*)&s_yA[n * 4];
                const float4 yb = *(const float4*)&s_yB[n * 4];
                sum[0] += ex2(d * kk[0]);
                sum[1] = fmaf(ex2(d * kk[1]), ya.x, sum[1]);
                sum[2] = fmaf(ex2(d * kk[2]), ya.y, sum[2]);
                sum[3] = fmaf(ex2(d * kk[3]), ya.z, sum[3]);
                sum[4] = fmaf(ex2(d * kk[4]), ya.w, sum[4]);
                sum[5] = fmaf(ex2(d * kk[5]), yb.x, sum[5]);
                sum[6] = fmaf(ex2(d * kk[6]), yb.y, sum[6]);
                sum[7] = fmaf(ex2(d * kk[7]), yb.z, sum[7]);
                sum[8] = fmaf(ex2(d * kk[8]), yb.w, sum[8]);
            }
        }
        __syncthreads();   // chunk consumed before restage
    }

    if (same) {
        float lo, hi;
        unpack2(dd0, lo, hi);  sum[0] = lo + hi;
        unpack2(A12, sum[1], sum[2]); unpack2(A34, sum[3], sum[4]);
        unpack2(A56, sum[5], sum[6]); unpack2(A78, sum[7], sum[8]);
    }

    #pragma unroll
    for (int c = 0; c < CREP; c++)
        s_red[(w * TGRP + lane) * CREP + c] = sum[c];
    __syncthreads();

    for (int i = tid; i < TGRP * CREP; i += NTHREADS) {
        float s = 0.0f;
        #pragma unroll
        for (int ww = 0; ww < WARPS; ww++)
            s += s_red[ww * (TGRP * CREP) + i];
        s_tot[i] = s;
    }
    __syncthreads();

    // GEMV: 32 m x 16 o = 512 outputs, 2 per thread; scatter by original index.
    #pragma unroll
    for (int k = 0; k < 2; k++) {
        const int idx = tid + k * NTHREADS;
        const int mm  = idx >> 4;
        const int o   = idx & (COUT - 1);
        const float density = s_tot[mm * CREP];
        const float inv = 1.0f / (density + 1e-8f);
        float r = __ldg(&gbias[o]) + __ldg(&gW[o * CREP]) * density;
        #pragma unroll
        for (int c = 1; c < CREP; c++)
            r = fmaf(__ldg(&gW[o * CREP + c]), s_tot[mm * CREP + c] * inv, r);
        gout[((size_t)b * MVAL + s_midx[mm]) * COUT + o] = r;
    }
}

extern "C" void kernel_launch(void* const* d_in, const int* in_sizes, int n_in,
                              void* d_out, int out_size) {
    const float* x     = (const float*)d_in[0];
    const float* y     = (const float*)d_in[1];
    const float* t     = (const float*)d_in[2];
    const float* sigma = (const float*)d_in[3];
    const float* W     = (const float*)d_in[4];
    const float* bias  = (const float*)d_in[5];
    float* out = (float*)d_out;

    convcnp_sort<<<B_ * 2, 1024>>>(x, y, t);                    // 16 blocks
    convcnp_main<<<B_ * NGRP, NTHREADS>>>(sigma, W, bias, out); // 256 blocks
}